// round 6
// baseline (speedup 1.0000x reference)
#include <cuda_runtime.h>

#define NN 100000
#define NE 3200000
#define DD 64
#define EPSBN 1e-5f
#define CHUNK 512
#define NCHUNK ((NN + CHUNK - 1) / CHUNK)   // 196

// ---------------- scratch (no allocations allowed) ----------------
__device__ int   g_deg[NN];
__device__ int   g_off[NN + 1];
__device__ int   g_cursor[NN];
__device__ int   g_csum[256];
__device__ int   g_coff[256];
__device__ float g_dinv[NN];
__device__ int2  g_entries[NE];           // {src, weight-bits}
__device__ float g_h[(size_t)NN * DD];    // bnrelu(y1) materialized
__device__ float g_agg[(size_t)NN * DD];
__device__ float g_y[(size_t)NN * DD];
__device__ float g_stats[2 * DD];
__device__ float g_bn[2 * DD];
__device__ float g_wc[DD * DD];           // combined W@fw
__device__ float g_bc[DD];                // combined bias

// ---------------- CSR build ----------------
__global__ void k_zero_deg() {
    int i = blockIdx.x * blockDim.x + threadIdx.x;
    if (i < NN) g_deg[i] = 0;
}
__global__ void k_hist(const int* __restrict__ dst) {
    int e = blockIdx.x * blockDim.x + threadIdx.x;
    if (e < NE) atomicAdd(&g_deg[dst[e]], 1);
}
__global__ void k_scan1() {
    __shared__ int sh[CHUNK];
    int c = blockIdx.x, t = threadIdx.x;
    int i = c * CHUNK + t;
    int val = (i < NN) ? g_deg[i] : 0;
    sh[t] = val;
    __syncthreads();
    #pragma unroll
    for (int o = 1; o < CHUNK; o <<= 1) {
        int x = (t >= o) ? sh[t - o] : 0;
        __syncthreads();
        sh[t] += x;
        __syncthreads();
    }
    if (i < NN) g_off[i] = sh[t] - val;
    if (t == CHUNK - 1) g_csum[c] = sh[t];
}
__global__ void k_scan2() {
    __shared__ int sh[256];
    int t = threadIdx.x;
    int val = (t < NCHUNK) ? g_csum[t] : 0;
    sh[t] = val;
    __syncthreads();
    #pragma unroll
    for (int o = 1; o < 256; o <<= 1) {
        int x = (t >= o) ? sh[t - o] : 0;
        __syncthreads();
        sh[t] += x;
        __syncthreads();
    }
    g_coff[t] = sh[t] - val;
}
__global__ void k_scan3() {
    int i = blockIdx.x * blockDim.x + threadIdx.x;
    if (i < NN) {
        int v = g_off[i] + g_coff[i / CHUNK];
        g_off[i] = v;
        g_cursor[i] = v;
        g_dinv[i] = rsqrtf((float)(g_deg[i] + 1));   // +1 self loop
        if (i == 0) g_off[NN] = NE;
    }
}
__global__ void k_scatter(const int* __restrict__ src, const int* __restrict__ dst) {
    int e = blockIdx.x * blockDim.x + threadIdx.x;
    if (e >= NE) return;
    int s = src[e], d = dst[e];
    float w = g_dinv[s] * g_dinv[d];
    int pos = atomicAdd(&g_cursor[d], 1);
    g_entries[pos] = make_int2(s, __float_as_int(w));
}

// ---------------- weight combine: Wc = W@fw, bc = b@fw + fb; zero stats ---
__global__ void k_combine(const float* __restrict__ W, const float* __restrict__ fw,
                          const float* __restrict__ b, const float* __restrict__ fb) {
    int col = threadIdx.x;          // 0..63
    int rb  = threadIdx.y * 4;      // row base, y in 0..15
    float acc[4] = {0.f, 0.f, 0.f, 0.f};
    for (int k = 0; k < DD; k++) {
        float f = fw[k * DD + col];
        #pragma unroll
        for (int r = 0; r < 4; r++) acc[r] += W[(rb + r) * DD + k] * f;
    }
    #pragma unroll
    for (int r = 0; r < 4; r++) g_wc[(rb + r) * DD + col] = acc[r];
    if (threadIdx.y == 0) {
        float s = fb[col];
        for (int k = 0; k < DD; k++) s += b[k] * fw[k * DD + col];
        g_bc[col] = s;
    }
    if (threadIdx.y == 1) {                 // fold stats zeroing in
        g_stats[col] = 0.f;
        g_stats[64 + col] = 0.f;
    }
}

// ---------------- aggregation: gather over CSR, self loop folded ----------
__global__ void __launch_bounds__(256) k_agg(const float* __restrict__ h,
                                             float* __restrict__ agg) {
    int node = blockIdx.x * 16 + (threadIdx.x >> 4);
    int q = threadIdx.x & 15;
    if (node >= NN) return;

    int beg = g_off[node];
    int end = g_off[node + 1];
    float di = g_dinv[node];
    float ww = di * di;

    float4 a = *reinterpret_cast<const float4*>(h + (size_t)node * DD + q * 4);
    float4 acc = make_float4(ww * a.x, ww * a.y, ww * a.z, ww * a.w);

    int e = beg;
    for (; e + 4 <= end; e += 4) {
        int2 e0 = g_entries[e];
        int2 e1 = g_entries[e + 1];
        int2 e2 = g_entries[e + 2];
        int2 e3 = g_entries[e + 3];
        float4 v0 = *reinterpret_cast<const float4*>(h + (size_t)e0.x * DD + q * 4);
        float4 v1 = *reinterpret_cast<const float4*>(h + (size_t)e1.x * DD + q * 4);
        float4 v2 = *reinterpret_cast<const float4*>(h + (size_t)e2.x * DD + q * 4);
        float4 v3 = *reinterpret_cast<const float4*>(h + (size_t)e3.x * DD + q * 4);
        float w0 = __int_as_float(e0.y), w1 = __int_as_float(e1.y);
        float w2 = __int_as_float(e2.y), w3 = __int_as_float(e3.y);
        acc.x += w0 * v0.x + w1 * v1.x + w2 * v2.x + w3 * v3.x;
        acc.y += w0 * v0.y + w1 * v1.y + w2 * v2.y + w3 * v3.y;
        acc.z += w0 * v0.z + w1 * v1.z + w2 * v2.z + w3 * v3.z;
        acc.w += w0 * v0.w + w1 * v1.w + w2 * v2.w + w3 * v3.w;
    }
    for (; e < end; e++) {
        int2 e0 = g_entries[e];
        float w0 = __int_as_float(e0.y);
        float4 v0 = *reinterpret_cast<const float4*>(h + (size_t)e0.x * DD + q * 4);
        acc.x += w0 * v0.x;
        acc.y += w0 * v0.y;
        acc.z += w0 * v0.z;
        acc.w += w0 * v0.w;
    }
    *reinterpret_cast<float4*>(agg + (size_t)node * DD + q * 4) = acc;
}

// ---------------- GEMM: out[N,64] = in[N,64] @ g_wc + g_bc, col stats -----
// inner loop uses packed fp32x2 FMA (FFMA2) — 8 packed accumulators
__global__ void __launch_bounds__(256) k_gemm(const float* __restrict__ in,
                                              float* __restrict__ out) {
    __shared__ float Xt[DD * 68];
    __shared__ float Ws[DD * DD];
    __shared__ float sred[2][4][DD];

    const int col = threadIdx.x;
    const int rg  = threadIdx.y;
    const int tid = rg * 64 + col;
    const int r0  = blockIdx.x * 64;

    #pragma unroll
    for (int it = 0; it < 4; it++) {
        int fi = (tid + it * 256) * 4;
        *reinterpret_cast<float4*>(&Ws[fi]) =
            *reinterpret_cast<const float4*>(&g_wc[fi]);
    }
    #pragma unroll
    for (int it = 0; it < 4; it++) {
        int fi = (tid + it * 256) * 4;
        int r = fi >> 6;
        int c = fi & 63;
        float4 v;
        if (r0 + r < NN)
            v = *reinterpret_cast<const float4*>(&in[(size_t)(r0 + r) * DD + c]);
        else
            v = make_float4(0.f, 0.f, 0.f, 0.f);
        Xt[(c + 0) * 68 + r] = v.x;
        Xt[(c + 1) * 68 + r] = v.y;
        Xt[(c + 2) * 68 + r] = v.z;
        Xt[(c + 3) * 68 + r] = v.w;
    }
    __syncthreads();

    unsigned long long accp[8];
    #pragma unroll
    for (int r = 0; r < 8; r++) accp[r] = 0ull;

    #pragma unroll 4
    for (int k = 0; k < DD; k++) {
        unsigned int wu = __float_as_uint(Ws[k * DD + col]);
        unsigned long long wp;
        asm("mov.b64 %0, {%1, %1};" : "=l"(wp) : "r"(wu));
        const ulonglong2* xp = reinterpret_cast<const ulonglong2*>(&Xt[k * 68 + rg * 16]);
        ulonglong2 a0 = xp[0], a1 = xp[1], a2 = xp[2], a3 = xp[3];
        asm("fma.rn.f32x2 %0, %1, %2, %0;" : "+l"(accp[0]) : "l"(a0.x), "l"(wp));
        asm("fma.rn.f32x2 %0, %1, %2, %0;" : "+l"(accp[1]) : "l"(a0.y), "l"(wp));
        asm("fma.rn.f32x2 %0, %1, %2, %0;" : "+l"(accp[2]) : "l"(a1.x), "l"(wp));
        asm("fma.rn.f32x2 %0, %1, %2, %0;" : "+l"(accp[3]) : "l"(a1.y), "l"(wp));
        asm("fma.rn.f32x2 %0, %1, %2, %0;" : "+l"(accp[4]) : "l"(a2.x), "l"(wp));
        asm("fma.rn.f32x2 %0, %1, %2, %0;" : "+l"(accp[5]) : "l"(a2.y), "l"(wp));
        asm("fma.rn.f32x2 %0, %1, %2, %0;" : "+l"(accp[6]) : "l"(a3.x), "l"(wp));
        asm("fma.rn.f32x2 %0, %1, %2, %0;" : "+l"(accp[7]) : "l"(a3.y), "l"(wp));
    }

    float ob = g_bc[col];
    float ps = 0.f, pss = 0.f;
    #pragma unroll
    for (int pr = 0; pr < 8; pr++) {
        unsigned int lo, hi;
        asm("mov.b64 {%0, %1}, %2;" : "=r"(lo), "=r"(hi) : "l"(accp[pr]));
        float v0 = __uint_as_float(lo), v1 = __uint_as_float(hi);
        int grow = r0 + rg * 16 + pr * 2;
        if (grow < NN) {
            float y = v0 + ob;
            out[(size_t)grow * DD + col] = y;
            ps += y; pss += y * y;
        }
        if (grow + 1 < NN) {
            float y = v1 + ob;
            out[(size_t)(grow + 1) * DD + col] = y;
            ps += y; pss += y * y;
        }
    }
    sred[0][rg][col] = ps;
    sred[1][rg][col] = pss;
    __syncthreads();
    if (rg == 0) {
        float s  = sred[0][0][col] + sred[0][1][col] + sred[0][2][col] + sred[0][3][col];
        float ss = sred[1][0][col] + sred[1][1][col] + sred[1][2][col] + sred[1][3][col];
        atomicAdd(&g_stats[col], s);
        atomicAdd(&g_stats[64 + col], ss);
    }
}

// ---------------- BN finalize / apply ----------------
__global__ void k_bn_fin(const float* __restrict__ g, const float* __restrict__ bt) {
    int c = threadIdx.x;
    float mu  = g_stats[c] * (1.0f / NN);
    float var = g_stats[64 + c] * (1.0f / NN) - mu * mu;
    float sc  = g[c] * rsqrtf(var + EPSBN);
    g_bn[c] = sc;
    g_bn[64 + c] = bt[c] - mu * sc;
}

__global__ void k_bn_relu_out(const float* __restrict__ y, float* __restrict__ out) {
    int i = blockIdx.x * blockDim.x + threadIdx.x;
    if (i < NN * DD) {
        int c = i & 63;
        out[i] = fmaxf(y[i] * g_bn[c] + g_bn[64 + c], 0.f);
    }
}

// ---------------- launch ----------------
extern "C" void kernel_launch(void* const* d_in, const int* in_sizes, int n_in,
                              void* d_out, int out_size) {
    const float* x   = (const float*)d_in[0];
    const int*   src = (const int*)d_in[1];
    const int*   dst = src + NE;
    const float *W1  = (const float*)d_in[2],  *b1  = (const float*)d_in[3];
    const float *fw1 = (const float*)d_in[4],  *fb1 = (const float*)d_in[5];
    const float *g1  = (const float*)d_in[6],  *bt1 = (const float*)d_in[7];
    const float *W2  = (const float*)d_in[8],  *b2  = (const float*)d_in[9];
    const float *fw2 = (const float*)d_in[10], *fb2 = (const float*)d_in[11];
    const float *g2  = (const float*)d_in[12], *bt2 = (const float*)d_in[13];
    float* out = (float*)d_out;

    float *ph, *pagg, *py;
    cudaGetSymbolAddress((void**)&ph,   g_h);
    cudaGetSymbolAddress((void**)&pagg, g_agg);
    cudaGetSymbolAddress((void**)&py,   g_y);

    const int T = 256;
    const int elemBlocks = (NN * DD + T - 1) / T;
    const int nodeBlocks = (NN + T - 1) / T;
    const int edgeBlocks = (NE + T - 1) / T;
    const int gemmBlocks = (NN + 63) / 64;
    const int aggBlocks  = (NN + 15) / 16;
    dim3 gB(64, 4);
    dim3 cB(64, 16);

    // ---- CSR build (once; shared by both layers) ----
    k_zero_deg<<<nodeBlocks, T>>>();
    k_hist<<<edgeBlocks, T>>>(dst);
    k_scan1<<<NCHUNK, CHUNK>>>();
    k_scan2<<<1, 256>>>();
    k_scan3<<<nodeBlocks, T>>>();
    k_scatter<<<edgeBlocks, T>>>(src, dst);

    // ---- layer 1:  y1 = (Â x)(W1@fw1) + bc1 ----
    k_combine<<<1, cB>>>(W1, fw1, b1, fb1);       // also zeroes stats
    k_agg<<<aggBlocks, T>>>(x, pagg);
    k_gemm<<<gemmBlocks, gB>>>(pagg, py);
    k_bn_fin<<<1, 64>>>(g1, bt1);

    // ---- layer 2:  y2 = (Â bnrelu(y1))(W2@fw2) + bc2 ----
    k_combine<<<1, cB>>>(W2, fw2, b2, fb2);       // also zeroes stats
    k_bn_relu_out<<<elemBlocks, T>>>(py, ph);     // materialize bnrelu(y1) ONCE
    k_agg<<<aggBlocks, T>>>(ph, pagg);
    k_gemm<<<gemmBlocks, gB>>>(pagg, py);
    k_bn_fin<<<1, 64>>>(g2, bt2);
    k_bn_relu_out<<<elemBlocks, T>>>(py, out);
}